// round 8
// baseline (speedup 1.0000x reference)
#include <cuda_runtime.h>
#include <cstdint>

#define TOKENS    16384
#define DDIM      2048
#define NEXP      64
#define MTILE     128
#define NBLK      (TOKENS / MTILE)       // 128
#define KC        32
#define NCHUNK    (DDIM / KC)            // 64
#define ROWB      144                    // padded row stride (bytes): 36 floats
#define XBYTES    (MTILE * ROWB)         // 18432
#define WBYTES    (NEXP * ROWB)          // 9216
#define STAGE     (XBYTES + WBYTES)      // 27648
#define SMEM_BYTES (2 * STAGE)           // 55296
#define EPIPITCH  68                     // floats; epilogue smem pitch
#define IDX_COUNT (TOKENS * 2)

__device__ float g_partials[NBLK * NEXP];   // usage partials (32 KB)

// ---------------- PTX helpers (base sm_103-safe) ----------------
__device__ __forceinline__ uint32_t smem_u32(const void* p) {
    uint32_t a;
    asm("{ .reg .u64 t; cvta.to.shared.u64 t, %1; cvt.u32.u64 %0, t; }" : "=r"(a) : "l"(p));
    return a;
}
__device__ __forceinline__ uint32_t tf32_rna(float f) {
    uint32_t r; asm("cvt.rna.tf32.f32 %0, %1;" : "=r"(r) : "f"(f)); return r;
}
__device__ __forceinline__ void cpa16(uint32_t dst, const void* src) {
    asm volatile("cp.async.cg.shared.global [%0], [%1], 16;" :: "r"(dst), "l"(src) : "memory");
}
__device__ __forceinline__ void cpa_commit() {
    asm volatile("cp.async.commit_group;" ::: "memory");
}
__device__ __forceinline__ void cpa_wait1() {
    asm volatile("cp.async.wait_group 1;" ::: "memory");
}
__device__ __forceinline__ void ldsm_x4(uint32_t* r, uint32_t addr) {
    asm volatile("ldmatrix.sync.aligned.m8n8.x4.shared.b16 {%0,%1,%2,%3}, [%4];"
                 : "=r"(r[0]), "=r"(r[1]), "=r"(r[2]), "=r"(r[3]) : "r"(addr));
}
__device__ __forceinline__ void mma_tf32(float* d, const uint32_t* a, const uint32_t* b) {
    asm volatile(
        "mma.sync.aligned.m16n8k8.row.col.f32.tf32.tf32.f32 "
        "{%0,%1,%2,%3}, {%4,%5,%6,%7}, {%8,%9}, {%0,%1,%2,%3};"
        : "+f"(d[0]), "+f"(d[1]), "+f"(d[2]), "+f"(d[3])
        : "r"(a[0]), "r"(a[1]), "r"(a[2]), "r"(a[3]), "r"(b[0]), "r"(b[1]));
}

// ============================================================================
// K1: fused 3xTF32 mma.sync GEMM + per-token top-2/softmax epilogue.
// 128 blocks x 256 threads. Block tile: M=128 tokens x N=64 experts x K=2048.
// Warp w owns the m16 group of tokens [w*16, (w+1)*16). Raw x and raw W are
// cp.async double-buffered; the tf32 hi/lo split happens in registers.
// Epilogue is strictly masked to tid < MTILE (128 tokens).
// ============================================================================
__global__ __launch_bounds__(256)
void k1_fused(const float* __restrict__ x, const float* __restrict__ W,
              float* __restrict__ out, int out_size) {
    extern __shared__ char dsm[];
    const int tid  = threadIdx.x;
    const int lane = tid & 31;
    const int w    = tid >> 5;
    const int tok0 = blockIdx.x * MTILE;
    const uint32_t sb = smem_u32(dsm);

    // cp.async staging descriptors (per chunk: advance src by KC floats)
    const float* xsrc[4]; uint32_t xdst[4];
#pragma unroll
    for (int i = 0; i < 4; i++) {
        int f = tid + 256 * i, row = f >> 3, c4 = f & 7;    // 1024 float4 = 128 rows
        xsrc[i] = x + (size_t)(tok0 + row) * DDIM + c4 * 4;
        xdst[i] = (uint32_t)(row * ROWB + c4 * 16);
    }
    const float* wsrc[2]; uint32_t wdst[2];
#pragma unroll
    for (int i = 0; i < 2; i++) {
        int f = tid + 256 * i, row = f >> 3, c4 = f & 7;    // 512 float4 = 64 rows
        wsrc[i] = W + (size_t)row * DDIM + c4 * 4;
        wdst[i] = (uint32_t)(XBYTES + row * ROWB + c4 * 16);
    }

    // ldmatrix per-lane offsets (verified mapping from round 6)
    const int rowin = lane & 7;
    const uint32_t aoff = (uint32_t)((rowin + ((lane >> 3) & 1) * 8) * ROWB + ((lane >> 4) & 1) * 16);
    const uint32_t boff = (uint32_t)((rowin + ((lane >> 4) & 1) * 8) * ROWB + ((lane >> 3) & 1) * 16);

    float acc[8][4];
#pragma unroll
    for (int n = 0; n < 8; n++)
#pragma unroll
        for (int r = 0; r < 4; r++) acc[n][r] = 0.0f;

    // Prologue: stage chunks 0 and 1
#pragma unroll
    for (int st = 0; st < 2; st++) {
        const uint32_t B = sb + st * STAGE;
#pragma unroll
        for (int i = 0; i < 4; i++) cpa16(B + xdst[i], xsrc[i] + st * KC);
#pragma unroll
        for (int i = 0; i < 2; i++) cpa16(B + wdst[i], wsrc[i] + st * KC);
        cpa_commit();
    }

    for (int c = 0; c < NCHUNK; c++) {
        cpa_wait1();
        __syncthreads();

        const uint32_t XS = sb + (c & 1) * STAGE;
        const uint32_t WS = XS + XBYTES;

#pragma unroll
        for (int ks = 0; ks < 4; ks++) {
            // A fragment: raw x via ldmatrix -> tf32 split in regs
            uint32_t Ah[4], Al[4];
            {
                uint32_t ar[4];
                ldsm_x4(ar, XS + (uint32_t)(w * 16 * ROWB + ks * 32) + aoff);
#pragma unroll
                for (int r = 0; r < 4; r++) {
                    float xf = __uint_as_float(ar[r]);
                    uint32_t h = tf32_rna(xf);
                    Ah[r] = h;
                    Al[r] = tf32_rna(xf - __uint_as_float(h));
                }
            }
            // B fragments: raw W via ldmatrix -> tf32 split in regs
            uint32_t Bh[8][2], Bl[8][2];
#pragma unroll
            for (int np = 0; np < 4; np++) {
                uint32_t t[4];
                ldsm_x4(t, WS + (uint32_t)(np * 16 * ROWB + ks * 32) + boff);
#pragma unroll
                for (int q = 0; q < 4; q++) {
                    float wf = __uint_as_float(t[q]);
                    uint32_t h = tf32_rna(wf);
                    Bh[2 * np + (q >> 1)][q & 1] = h;
                    Bl[2 * np + (q >> 1)][q & 1] = tf32_rna(wf - __uint_as_float(h));
                }
            }
            // 3xTF32: AhBh + AhBl + AlBh
#pragma unroll
            for (int n = 0; n < 8; n++) {
                mma_tf32(acc[n], Ah, Bh[n]);
                mma_tf32(acc[n], Ah, Bl[n]);
                mma_tf32(acc[n], Al, Bh[n]);
            }
        }

        __syncthreads();
        if (c + 2 < NCHUNK) {
            const uint32_t B = sb + (c & 1) * STAGE;
            const int o = (c + 2) * KC;
#pragma unroll
            for (int i = 0; i < 4; i++) cpa16(B + xdst[i], xsrc[i] + o);
#pragma unroll
            for (int i = 0; i < 2; i++) cpa16(B + wdst[i], wsrc[i] + o);
        }
        cpa_commit();
    }
    __syncthreads();

    // ---- fused epilogue ----
    // 1) accumulators -> smem logits [128 tokens][EPIPITCH floats]
    //    (34 KB, fits in the 55 KB dynamic smem window)
    float* lgs = reinterpret_cast<float*>(dsm);
    {
        const int r0 = w * 16 + (lane >> 2);
        const int cb = (lane & 3) * 2;
#pragma unroll
        for (int n = 0; n < 8; n++) {
            const int col = n * 8 + cb;
            *reinterpret_cast<float2*>(lgs + r0 * EPIPITCH + col) =
                make_float2(acc[n][0], acc[n][1]);
            *reinterpret_cast<float2*>(lgs + (r0 + 8) * EPIPITCH + col) =
                make_float2(acc[n][2], acc[n][3]);
        }
    }
    __syncthreads();

    // 2) one thread per TOKEN (tid < MTILE): top-2 + softmax + outputs,
    //    then write normalized probs back into its own row (thread-private).
    if (tid < MTILE) {
        float* row = lgs + tid * EPIPITCH;
        float lg[64];
#pragma unroll
        for (int e = 0; e < NEXP; e++) lg[e] = row[e];

        float v1 = -1e30f, v2 = -1e30f; int j1 = 0, j2 = 0;
#pragma unroll
        for (int e = 0; e < NEXP; e++) {
            float l = lg[e];
            if (l > v1)      { v2 = v1; j2 = j1; v1 = l; j1 = e; }
            else if (l > v2) { v2 = l;  j2 = e; }
        }
        float s = 0.0f;
#pragma unroll
        for (int e = 0; e < NEXP; e++) { float p = __expf(lg[e] - v1); lg[e] = p; s += p; }
        const float inv = 1.0f / s;

        const int t = tok0 + tid;
        out[t * 2]                 = (float)j1;
        out[t * 2 + 1]             = (float)j2;
        const float w1 = 1.0f / (1.0f + __expf(v2 - v1));
        out[IDX_COUNT + t * 2]     = w1;
        out[IDX_COUNT + t * 2 + 1] = 1.0f - w1;

        // store normalized prob row (only this thread touches row tid)
#pragma unroll
        for (int e = 0; e < NEXP; e++) row[e] = lg[e] * inv;
    }
    __syncthreads();

    // 3) deterministic per-block usage partials (fixed order over 128 rows)
    if (tid < NEXP) {
        float u = 0.0f;
        for (int r = 0; r < MTILE; r++) u += lgs[r * EPIPITCH + tid];
        g_partials[blockIdx.x * NEXP + tid] = u;
    }
}

// ============================================================================
// K3: aux loss over 128 block partials (deterministic, tiny).
// ============================================================================
__global__ __launch_bounds__(64)
void k3_aux(float* __restrict__ out, int out_size) {
    __shared__ float red[NEXP];
    const int e = threadIdx.x;
    float u = 0.0f;
#pragma unroll 4
    for (int b = 0; b < NBLK; b++) u += g_partials[b * NEXP + e];
    float dd = u * (1.0f / (float)TOKENS) - (1.0f / (float)NEXP);
    red[e] = dd * dd;
    __syncthreads();
    if (e == 0) {
        float a = 0.0f;
#pragma unroll
        for (int i = 0; i < NEXP; i++) a += red[i];
        if (out_size > 2 * IDX_COUNT) out[out_size - 1] = a;
    }
}

// ============================================================================
extern "C" void kernel_launch(void* const* d_in, const int* in_sizes, int n_in,
                              void* d_out, int out_size) {
    const float* x = (const float*)d_in[0];   // [16384, 2048]
    const float* W = (const float*)d_in[1];   // [64, 2048]
    float* out = (float*)d_out;

    cudaFuncSetAttribute(k1_fused, cudaFuncAttributeMaxDynamicSharedMemorySize, SMEM_BYTES);

    k1_fused<<<NBLK, 256, SMEM_BYTES>>>(x, W, out, out_size);
    k3_aux<<<1, 64>>>(out, out_size);
}

// round 9
// speedup vs baseline: 1.1943x; 1.1943x over previous
#include <cuda_runtime.h>
#include <cstdint>

#define TOKENS    16384
#define DDIM      2048
#define NEXP      64
#define MTILE     128
#define NBLK      (TOKENS / MTILE)       // 128
#define KC        32
#define NCHUNK    (DDIM / KC)            // 64
#define ROWB      144                    // padded row stride (bytes): 36 floats
#define XBYTES    (MTILE * ROWB)         // 18432
#define WBYTES    (NEXP * ROWB)          // 9216
#define STAGE     (XBYTES + 2 * WBYTES)  // 36864
#define SMEM_BYTES (2 * STAGE)           // 73728
#define EPIPITCH  68                     // floats; epilogue smem pitch
#define IDX_COUNT (TOKENS * 2)

__device__ uint32_t g_Whi[NEXP * DDIM];     // tf32 hi (512 KB)
__device__ uint32_t g_Wlo[NEXP * DDIM];     // tf32 lo (512 KB)
__device__ float    g_partials[NBLK * NEXP];

// ---------------- PTX helpers (base sm_103-safe) ----------------
__device__ __forceinline__ uint32_t smem_u32(const void* p) {
    uint32_t a;
    asm("{ .reg .u64 t; cvta.to.shared.u64 t, %1; cvt.u32.u64 %0, t; }" : "=r"(a) : "l"(p));
    return a;
}
__device__ __forceinline__ uint32_t tf32_rna(float f) {
    uint32_t r; asm("cvt.rna.tf32.f32 %0, %1;" : "=r"(r) : "f"(f)); return r;
}
__device__ __forceinline__ void cpa16(uint32_t dst, const void* src) {
    asm volatile("cp.async.cg.shared.global [%0], [%1], 16;" :: "r"(dst), "l"(src) : "memory");
}
__device__ __forceinline__ void cpa_commit() {
    asm volatile("cp.async.commit_group;" ::: "memory");
}
__device__ __forceinline__ void cpa_wait1() {
    asm volatile("cp.async.wait_group 1;" ::: "memory");
}
__device__ __forceinline__ void ldsm_x4(uint32_t* r, uint32_t addr) {
    asm volatile("ldmatrix.sync.aligned.m8n8.x4.shared.b16 {%0,%1,%2,%3}, [%4];"
                 : "=r"(r[0]), "=r"(r[1]), "=r"(r[2]), "=r"(r[3]) : "r"(addr));
}
__device__ __forceinline__ void mma_tf32(float* d, const uint32_t* a, const uint32_t* b) {
    asm volatile(
        "mma.sync.aligned.m16n8k8.row.col.f32.tf32.tf32.f32 "
        "{%0,%1,%2,%3}, {%4,%5,%6,%7}, {%8,%9}, {%0,%1,%2,%3};"
        : "+f"(d[0]), "+f"(d[1]), "+f"(d[2]), "+f"(d[3])
        : "r"(a[0]), "r"(a[1]), "r"(a[2]), "r"(a[3]), "r"(b[0]), "r"(b[1]));
}

// ============================================================================
// K0: pre-split W into tf32 hi/lo once (removes 8x-redundant in-loop W cvt).
// ============================================================================
__global__ __launch_bounds__(256)
void k0_split(const float* __restrict__ W) {
    int i = blockIdx.x * 256 + threadIdx.x;
    if (i < NEXP * DDIM) {
        float w = W[i];
        uint32_t h = tf32_rna(w);
        g_Whi[i] = h;
        g_Wlo[i] = tf32_rna(w - __uint_as_float(h));
    }
}

// ============================================================================
// K1: fused 3xTF32 mma.sync GEMM + per-token top-2/softmax epilogue.
// 128 blocks x 256 threads; tile M=128 x N=64 x K=2048.
// Warp w owns the m16 token group [w*16,(w+1)*16). Staged per chunk: raw x
// (tf32-split in regs) + pre-split W hi/lo planes. cp.async double-buffered.
// ============================================================================
__global__ __launch_bounds__(256)
void k1_fused(const float* __restrict__ x,
              float* __restrict__ out, int out_size) {
    extern __shared__ char dsm[];
    const int tid  = threadIdx.x;
    const int lane = tid & 31;
    const int w    = tid >> 5;
    const int tok0 = blockIdx.x * MTILE;
    const uint32_t sb = smem_u32(dsm);

    // cp.async staging descriptors (per chunk: advance src by KC floats)
    const float* xsrc[4]; uint32_t xdst[4];
#pragma unroll
    for (int i = 0; i < 4; i++) {
        int f = tid + 256 * i, row = f >> 3, c4 = f & 7;    // 1024 float4 = 128 rows
        xsrc[i] = x + (size_t)(tok0 + row) * DDIM + c4 * 4;
        xdst[i] = (uint32_t)(row * ROWB + c4 * 16);
    }
    const float* wsrc[4]; uint32_t wdst[4];
#pragma unroll
    for (int i = 0; i < 4; i++) {
        int f = tid + 256 * i, row = (f >> 3) & 63, c4 = f & 7, arr = f >> 9;
        const uint32_t* wb = arr ? g_Wlo : g_Whi;
        wsrc[i] = (const float*)(wb + (size_t)row * DDIM + c4 * 4);
        wdst[i] = (uint32_t)(XBYTES + arr * WBYTES + row * ROWB + c4 * 16);
    }

    // ldmatrix per-lane offsets (verified mapping)
    const int rowin = lane & 7;
    const uint32_t aoff = (uint32_t)((rowin + ((lane >> 3) & 1) * 8) * ROWB + ((lane >> 4) & 1) * 16);
    const uint32_t boff = (uint32_t)((rowin + ((lane >> 4) & 1) * 8) * ROWB + ((lane >> 3) & 1) * 16);

    float acc[8][4];
#pragma unroll
    for (int n = 0; n < 8; n++)
#pragma unroll
        for (int r = 0; r < 4; r++) acc[n][r] = 0.0f;

    // Prologue: stage chunks 0 and 1
#pragma unroll
    for (int st = 0; st < 2; st++) {
        const uint32_t B = sb + st * STAGE;
#pragma unroll
        for (int i = 0; i < 4; i++) cpa16(B + xdst[i], xsrc[i] + st * KC);
#pragma unroll
        for (int i = 0; i < 4; i++) cpa16(B + wdst[i], wsrc[i] + st * KC);
        cpa_commit();
    }

    for (int c = 0; c < NCHUNK; c++) {
        cpa_wait1();
        __syncthreads();

        const uint32_t XS = sb + (c & 1) * STAGE;
        const uint32_t WH = XS + XBYTES;
        const uint32_t WL = WH + WBYTES;

#pragma unroll
        for (int ks = 0; ks < 4; ks++) {
            // A fragment: raw x via ldmatrix -> tf32 split in regs
            uint32_t Ah[4], Al[4];
            {
                uint32_t ar[4];
                ldsm_x4(ar, XS + (uint32_t)(w * 16 * ROWB + ks * 32) + aoff);
#pragma unroll
                for (int r = 0; r < 4; r++) {
                    float xf = __uint_as_float(ar[r]);
                    uint32_t h = tf32_rna(xf);
                    Ah[r] = h;
                    Al[r] = tf32_rna(xf - __uint_as_float(h));
                }
            }
            // B fragments: pre-split hi/lo planes, no cvt
            uint32_t Bh[8][2], Bl[8][2];
#pragma unroll
            for (int np = 0; np < 4; np++) {
                uint32_t t[4];
                ldsm_x4(t, WH + (uint32_t)(np * 16 * ROWB + ks * 32) + boff);
                Bh[2 * np][0] = t[0]; Bh[2 * np][1] = t[1];
                Bh[2 * np + 1][0] = t[2]; Bh[2 * np + 1][1] = t[3];
                ldsm_x4(t, WL + (uint32_t)(np * 16 * ROWB + ks * 32) + boff);
                Bl[2 * np][0] = t[0]; Bl[2 * np][1] = t[1];
                Bl[2 * np + 1][0] = t[2]; Bl[2 * np + 1][1] = t[3];
            }
            // 3xTF32: AhBh + AhBl + AlBh
#pragma unroll
            for (int n = 0; n < 8; n++) {
                mma_tf32(acc[n], Ah, Bh[n]);
                mma_tf32(acc[n], Ah, Bl[n]);
                mma_tf32(acc[n], Al, Bh[n]);
            }
        }

        __syncthreads();
        if (c + 2 < NCHUNK) {
            const uint32_t B = sb + (c & 1) * STAGE;
            const int o = (c + 2) * KC;
#pragma unroll
            for (int i = 0; i < 4; i++) cpa16(B + xdst[i], xsrc[i] + o);
#pragma unroll
            for (int i = 0; i < 4; i++) cpa16(B + wdst[i], wsrc[i] + o);
        }
        cpa_commit();
    }
    __syncthreads();

    // ---- fused epilogue ----
    // 1) accumulators -> smem logits [128 tokens][EPIPITCH floats] (34 KB)
    float* lgs = reinterpret_cast<float*>(dsm);
    {
        const int r0 = w * 16 + (lane >> 2);
        const int cb = (lane & 3) * 2;
#pragma unroll
        for (int n = 0; n < 8; n++) {
            const int col = n * 8 + cb;
            *reinterpret_cast<float2*>(lgs + r0 * EPIPITCH + col) =
                make_float2(acc[n][0], acc[n][1]);
            *reinterpret_cast<float2*>(lgs + (r0 + 8) * EPIPITCH + col) =
                make_float2(acc[n][2], acc[n][3]);
        }
    }
    __syncthreads();

    // 2) one thread per TOKEN (tid < MTILE): top-2 + softmax + outputs,
    //    then write normalized probs back into its own (thread-private) row.
    if (tid < MTILE) {
        float* row = lgs + tid * EPIPITCH;
        float lg[64];
#pragma unroll
        for (int e = 0; e < NEXP; e++) lg[e] = row[e];

        float v1 = -1e30f, v2 = -1e30f; int j1 = 0, j2 = 0;
#pragma unroll
        for (int e = 0; e < NEXP; e++) {
            float l = lg[e];
            if (l > v1)      { v2 = v1; j2 = j1; v1 = l; j1 = e; }
            else if (l > v2) { v2 = l;  j2 = e; }
        }
        float s = 0.0f;
#pragma unroll
        for (int e = 0; e < NEXP; e++) { float p = __expf(lg[e] - v1); lg[e] = p; s += p; }
        const float inv = 1.0f / s;

        const int t = tok0 + tid;
        out[t * 2]                 = (float)j1;
        out[t * 2 + 1]             = (float)j2;
        const float w1 = 1.0f / (1.0f + __expf(v2 - v1));
        out[IDX_COUNT + t * 2]     = w1;
        out[IDX_COUNT + t * 2 + 1] = 1.0f - w1;

#pragma unroll
        for (int e = 0; e < NEXP; e++) row[e] = lg[e] * inv;
    }
    __syncthreads();

    // 3) deterministic per-block usage partials (fixed order over 128 rows)
    if (tid < NEXP) {
        float u = 0.0f;
        for (int r = 0; r < MTILE; r++) u += lgs[r * EPIPITCH + tid];
        g_partials[blockIdx.x * NEXP + tid] = u;
    }
}

// ============================================================================
// K3: aux loss. 512 threads, 8-way partition -> 16 independent loads/thread
// (one latency batch), two-level deterministic reduction.
// ============================================================================
__global__ __launch_bounds__(512)
void k3_aux(float* __restrict__ out, int out_size) {
    __shared__ float red[512];
    const int tid  = threadIdx.x;
    const int e    = tid & 63;
    const int part = tid >> 6;   // 8 partitions over 128 blocks

    float s = 0.0f;
#pragma unroll
    for (int i = 0; i < NBLK / 8; i++)       // 16 independent loads
        s += g_partials[(part + 8 * i) * NEXP + e];
    red[tid] = s;
    __syncthreads();

    if (tid < NEXP) {
        float u = 0.0f;
#pragma unroll
        for (int p = 0; p < 8; p++) u += red[p * 64 + tid];
        float d = u * (1.0f / (float)TOKENS) - (1.0f / (float)NEXP);
        red[tid] = d * d;
    }
    __syncthreads();

    if (tid == 0) {
        float a = 0.0f;
#pragma unroll
        for (int i = 0; i < NEXP; i++) a += red[i];
        if (out_size > 2 * IDX_COUNT) out[out_size - 1] = a;
    }
}

// ============================================================================
extern "C" void kernel_launch(void* const* d_in, const int* in_sizes, int n_in,
                              void* d_out, int out_size) {
    const float* x = (const float*)d_in[0];   // [16384, 2048]
    const float* W = (const float*)d_in[1];   // [64, 2048]
    float* out = (float*)d_out;

    cudaFuncSetAttribute(k1_fused, cudaFuncAttributeMaxDynamicSharedMemorySize, SMEM_BYTES);

    k0_split<<<(NEXP * DDIM + 255) / 256, 256>>>(W);
    k1_fused<<<NBLK, 256, SMEM_BYTES>>>(x, out, out_size);
    k3_aux<<<1, 512>>>(out, out_size);
}

// round 10
// speedup vs baseline: 2.0177x; 1.6895x over previous
#include <cuda_runtime.h>
#include <cuda_fp16.h>
#include <cstdint>

#define TOKENS    16384
#define DDIM      2048
#define NEXP      64
#define MTILE     128
#define NBLK      (TOKENS / MTILE)       // 128
#define KC        32
#define NCHUNK    (DDIM / KC)            // 64
#define XROWB     160                    // x fp32 row stride (bytes): conflict-free LDS.64
#define XBYTES    (MTILE * XROWB)        // 20480
#define WROWB     80                     // W fp16 plane row stride (bytes): conflict-free ldsm
#define WPBYTES   (NEXP * WROWB)         // 5120 per plane
#define STAGE     (XBYTES + 2 * WPBYTES) // 30720
#define SMEM_BYTES (2 * STAGE)           // 61440
#define EPIPITCH  68                     // floats; epilogue smem pitch
#define IDX_COUNT (TOKENS * 2)
#define LO_SCALE  2048.0f
#define LO_INV    (1.0f / 2048.0f)

__device__ __half g_Whi[NEXP * DDIM];       // fp16 hi plane (256 KB)
__device__ __half g_Wlo[NEXP * DDIM];       // fp16 lo plane, pre-scaled by 2^11
__device__ float  g_partials[NBLK * NEXP];

// ---------------- PTX helpers (base sm_103-safe) ----------------
__device__ __forceinline__ uint32_t smem_u32(const void* p) {
    uint32_t a;
    asm("{ .reg .u64 t; cvta.to.shared.u64 t, %1; cvt.u32.u64 %0, t; }" : "=r"(a) : "l"(p));
    return a;
}
__device__ __forceinline__ void cpa16(uint32_t dst, const void* src) {
    asm volatile("cp.async.cg.shared.global [%0], [%1], 16;" :: "r"(dst), "l"(src) : "memory");
}
__device__ __forceinline__ void cpa_commit() {
    asm volatile("cp.async.commit_group;" ::: "memory");
}
__device__ __forceinline__ void cpa_wait1() {
    asm volatile("cp.async.wait_group 1;" ::: "memory");
}
__device__ __forceinline__ void ldsm_x4(uint32_t* r, uint32_t addr) {
    asm volatile("ldmatrix.sync.aligned.m8n8.x4.shared.b16 {%0,%1,%2,%3}, [%4];"
                 : "=r"(r[0]), "=r"(r[1]), "=r"(r[2]), "=r"(r[3]) : "r"(addr));
}
__device__ __forceinline__ void lds64(float2& v, uint32_t addr) {
    asm volatile("ld.shared.v2.f32 {%0,%1}, [%2];" : "=f"(v.x), "=f"(v.y) : "r"(addr));
}
__device__ __forceinline__ void mma_f16(float* d, const uint32_t* a, const uint32_t* b) {
    asm volatile(
        "mma.sync.aligned.m16n8k16.row.col.f32.f16.f16.f32 "
        "{%0,%1,%2,%3}, {%4,%5,%6,%7}, {%8,%9}, {%0,%1,%2,%3};"
        : "+f"(d[0]), "+f"(d[1]), "+f"(d[2]), "+f"(d[3])
        : "r"(a[0]), "r"(a[1]), "r"(a[2]), "r"(a[3]), "r"(b[0]), "r"(b[1]));
}
// split float2 -> packed fp16 hi + packed fp16 lo*2048 (tf32-equivalent precision)
__device__ __forceinline__ void split_f16(float2 v, uint32_t& hi, uint32_t& lo) {
    __half2 h = __float22half2_rn(v);                 // x->low, y->high
    float2  hf = __half22float2(h);
    __half2 l = __float22half2_rn(
        make_float2((v.x - hf.x) * LO_SCALE, (v.y - hf.y) * LO_SCALE));
    hi = *reinterpret_cast<uint32_t*>(&h);
    lo = *reinterpret_cast<uint32_t*>(&l);
}

// ============================================================================
// K0: pre-split W into fp16 hi + scaled lo planes.
// ============================================================================
__global__ __launch_bounds__(256)
void k0_split(const float* __restrict__ W) {
    int i = blockIdx.x * 256 + threadIdx.x;
    if (i < NEXP * DDIM) {
        float w = W[i];
        __half h = __float2half_rn(w);
        g_Whi[i] = h;
        g_Wlo[i] = __float2half_rn((w - __half2float(h)) * LO_SCALE);
    }
}

// ============================================================================
// K1: fused 3xFP16 (hi/lo, lo scaled 2^11) mma.sync GEMM + fused epilogue.
// 128 blocks x 256 threads; tile M=128 x N=64 x K=2048, m16n8k16 HMMA.
// accH += Ah*Bh ; accL += Ah*Bl' + Al'*Bh ; logit = accH + accL/2048.
// ============================================================================
__global__ __launch_bounds__(256)
void k1_fused(const float* __restrict__ x,
              float* __restrict__ out, int out_size) {
    extern __shared__ char dsm[];
    const int tid  = threadIdx.x;
    const int lane = tid & 31;
    const int w    = tid >> 5;
    const int tok0 = blockIdx.x * MTILE;
    const uint32_t sb = smem_u32(dsm);

    // cp.async staging descriptors
    const float* xsrc[4]; uint32_t xdst[4];
#pragma unroll
    for (int i = 0; i < 4; i++) {
        int f = tid + 256 * i, row = f >> 3, c4 = f & 7;    // 1024 x 16B = 128 rows x 32 floats
        xsrc[i] = x + (size_t)(tok0 + row) * DDIM + c4 * 4;
        xdst[i] = (uint32_t)(row * XROWB + c4 * 16);
    }
    const __half* wsrc[2]; uint32_t wdst[2];
#pragma unroll
    for (int i = 0; i < 2; i++) {
        int f = tid, row = f >> 2, c4 = f & 3;              // 256 x 16B = 64 rows x 32 halfs
        const __half* plane = i ? g_Wlo : g_Whi;
        wsrc[i] = plane + (size_t)row * DDIM + c4 * 8;
        wdst[i] = (uint32_t)(XBYTES + i * WPBYTES + row * WROWB + c4 * 16);
    }

    // A LDS.64 base (fragment positions): row r = w*16 + lane/4, col pair (lane%4)*2
    const uint32_t abase = (uint32_t)((w * 16 + (lane >> 2)) * XROWB + (lane & 3) * 8);
    // B ldmatrix lane address offset within a plane
    const int brow = lane & 7, bsel = lane >> 3;
    const uint32_t blaneoff =
        (uint32_t)((brow + (bsel >> 1) * 8) * WROWB + (bsel & 1) * 16);

    float accH[8][4], accL[8][4];
#pragma unroll
    for (int n = 0; n < 8; n++)
#pragma unroll
        for (int r = 0; r < 4; r++) { accH[n][r] = 0.0f; accL[n][r] = 0.0f; }

    // Prologue: stage chunks 0 and 1
#pragma unroll
    for (int st = 0; st < 2; st++) {
        const uint32_t B = sb + st * STAGE;
#pragma unroll
        for (int i = 0; i < 4; i++) cpa16(B + xdst[i], xsrc[i] + st * KC);
#pragma unroll
        for (int i = 0; i < 2; i++) cpa16(B + wdst[i], wsrc[i] + st * KC);
        cpa_commit();
    }

    for (int c = 0; c < NCHUNK; c++) {
        cpa_wait1();
        __syncthreads();

        const uint32_t XS = sb + (c & 1) * STAGE;
        const uint32_t WH = XS + XBYTES;
        const uint32_t WL = WH + WPBYTES;

#pragma unroll
        for (int ks = 0; ks < 2; ks++) {          // two k16 steps per k32 chunk
            // A fragments: 4 x LDS.64 of fp32 x at fragment positions -> split
            uint32_t Ah[4], Al[4];
            {
                const uint32_t ab = XS + abase + ks * 64;
                float2 v00, v10, v01, v11;
                lds64(v00, ab);                       // (r,   k pair)
                lds64(v10, ab + 8 * XROWB);           // (r+8, k pair)
                lds64(v01, ab + 32);                  // (r,   k pair+8)
                lds64(v11, ab + 8 * XROWB + 32);      // (r+8, k pair+8)
                split_f16(v00, Ah[0], Al[0]);
                split_f16(v10, Ah[1], Al[1]);
                split_f16(v01, Ah[2], Al[2]);
                split_f16(v11, Ah[3], Al[3]);
            }
            // B fragments: ldmatrix.b16 on hi and lo planes (each x4 = 16 experts)
            uint32_t Bh[8][2], Bl[8][2];
#pragma unroll
            for (int np = 0; np < 4; np++) {
                uint32_t t[4];
                ldsm_x4(t, WH + (uint32_t)(np * 16 * WROWB + ks * 32) + blaneoff);
                Bh[2 * np][0] = t[0]; Bh[2 * np][1] = t[1];
                Bh[2 * np + 1][0] = t[2]; Bh[2 * np + 1][1] = t[3];
                ldsm_x4(t, WL + (uint32_t)(np * 16 * WROWB + ks * 32) + blaneoff);
                Bl[2 * np][0] = t[0]; Bl[2 * np][1] = t[1];
                Bl[2 * np + 1][0] = t[2]; Bl[2 * np + 1][1] = t[3];
            }
            // 3 terms: hi*hi -> accH ; hi*lo' + lo'*hi -> accL
#pragma unroll
            for (int n = 0; n < 8; n++) {
                mma_f16(accH[n], Ah, Bh[n]);
                mma_f16(accL[n], Ah, Bl[n]);
                mma_f16(accL[n], Al, Bh[n]);
            }
        }

        __syncthreads();
        if (c + 2 < NCHUNK) {
            const uint32_t B = sb + (c & 1) * STAGE;
            const int o = (c + 2) * KC;
#pragma unroll
            for (int i = 0; i < 4; i++) cpa16(B + xdst[i], xsrc[i] + o);
#pragma unroll
            for (int i = 0; i < 2; i++) cpa16(B + wdst[i], wsrc[i] + o);
        }
        cpa_commit();
    }
    __syncthreads();

    // ---- fused epilogue ----
    // 1) combine hi/lo accumulators -> smem logits [128][EPIPITCH] (34 KB)
    float* lgs = reinterpret_cast<float*>(dsm);
    {
        const int r0 = w * 16 + (lane >> 2);
        const int cb = (lane & 3) * 2;
#pragma unroll
        for (int n = 0; n < 8; n++) {
            const int col = n * 8 + cb;
            *reinterpret_cast<float2*>(lgs + r0 * EPIPITCH + col) =
                make_float2(accH[n][0] + accL[n][0] * LO_INV,
                            accH[n][1] + accL[n][1] * LO_INV);
            *reinterpret_cast<float2*>(lgs + (r0 + 8) * EPIPITCH + col) =
                make_float2(accH[n][2] + accL[n][2] * LO_INV,
                            accH[n][3] + accL[n][3] * LO_INV);
        }
    }
    __syncthreads();

    // 2) one thread per TOKEN: top-2 + softmax + outputs + prob row
    if (tid < MTILE) {
        float* row = lgs + tid * EPIPITCH;
        float lg[64];
#pragma unroll
        for (int e = 0; e < NEXP; e++) lg[e] = row[e];

        float v1 = -1e30f, v2 = -1e30f; int j1 = 0, j2 = 0;
#pragma unroll
        for (int e = 0; e < NEXP; e++) {
            float l = lg[e];
            if (l > v1)      { v2 = v1; j2 = j1; v1 = l; j1 = e; }
            else if (l > v2) { v2 = l;  j2 = e; }
        }
        float s = 0.0f;
#pragma unroll
        for (int e = 0; e < NEXP; e++) { float p = __expf(lg[e] - v1); lg[e] = p; s += p; }
        const float inv = 1.0f / s;

        const int t = tok0 + tid;
        out[t * 2]                 = (float)j1;
        out[t * 2 + 1]             = (float)j2;
        const float w1 = 1.0f / (1.0f + __expf(v2 - v1));
        out[IDX_COUNT + t * 2]     = w1;
        out[IDX_COUNT + t * 2 + 1] = 1.0f - w1;

#pragma unroll
        for (int e = 0; e < NEXP; e++) row[e] = lg[e] * inv;
    }
    __syncthreads();

    // 3) deterministic per-block usage partials
    if (tid < NEXP) {
        float u = 0.0f;
        for (int r = 0; r < MTILE; r++) u += lgs[r * EPIPITCH + tid];
        g_partials[blockIdx.x * NEXP + tid] = u;
    }
}

// ============================================================================
// K3: aux loss. 512 threads, 8-way partition, two-level deterministic reduce.
// ============================================================================
__global__ __launch_bounds__(512)
void k3_aux(float* __restrict__ out, int out_size) {
    __shared__ float red[512];
    const int tid  = threadIdx.x;
    const int e    = tid & 63;
    const int part = tid >> 6;

    float s = 0.0f;
#pragma unroll
    for (int i = 0; i < NBLK / 8; i++)
        s += g_partials[(part + 8 * i) * NEXP + e];
    red[tid] = s;
    __syncthreads();

    if (tid < NEXP) {
        float u = 0.0f;
#pragma unroll
        for (int p = 0; p < 8; p++) u += red[p * 64 + tid];
        float d = u * (1.0f / (float)TOKENS) - (1.0f / (float)NEXP);
        red[tid] = d * d;
    }
    __syncthreads();

    if (tid == 0) {
        float a = 0.0f;
#pragma unroll
        for (int i = 0; i < NEXP; i++) a += red[i];
        if (out_size > 2 * IDX_COUNT) out[out_size - 1] = a;
    }
}

// ============================================================================
extern "C" void kernel_launch(void* const* d_in, const int* in_sizes, int n_in,
                              void* d_out, int out_size) {
    const float* x = (const float*)d_in[0];   // [16384, 2048]
    const float* W = (const float*)d_in[1];   // [64, 2048]
    float* out = (float*)d_out;

    cudaFuncSetAttribute(k1_fused, cudaFuncAttributeMaxDynamicSharedMemorySize, SMEM_BYTES);

    k0_split<<<(NEXP * DDIM + 255) / 256, 256>>>(W);
    k1_fused<<<NBLK, 256, SMEM_BYTES>>>(x, out, out_size);
    k3_aux<<<1, 512>>>(out, out_size);
}